// round 13
// baseline (speedup 1.0000x reference)
#include <cuda_runtime.h>
#include <cuda_bf16.h>
#include <math.h>
#include <stdint.h>

#define N_NODES   50001
#define N_PAD     (N_NODES + 128)
#define N_NBRS    12
#define N_GRAPHS  1000
#define NEG_BIG   (-9000000000000000.0f)
#define HD        256

#define N_ROW_TILES ((N_NODES + 127) / 128)        // 391

// ---------------------------------------------------------------------------
// Scratch
// ---------------------------------------------------------------------------
__device__ float g_bufH[(size_t)N_NODES * HD];                  // GEMM out (fp32)
__device__ unsigned short g_nbh[(size_t)N_PAD * HD];            // GEMM out (bf16 hi) for gather
__device__ unsigned short g_ah[(size_t)N_PAD * HD];             // next-layer A hi (bf16)
__device__ unsigned short g_al[(size_t)N_PAD * HD];             // next-layer A lo (bf16)

#define WCH 8192                          // 256*32
#define WT_TOTAL (20 * WCH)
__device__ unsigned short g_wbh[WT_TOTAL];
__device__ unsigned short g_wbl[WT_TOTAL];

// ---------------------------------------------------------------------------
// helpers
// ---------------------------------------------------------------------------
__device__ __forceinline__ unsigned short f2bf(float v) {
    return __bfloat16_as_ushort(__float2bfloat16_rn(v));
}
__device__ __forceinline__ float bf2f(unsigned short u) {
    return __bfloat162float(__ushort_as_bfloat16(u));
}
__device__ __forceinline__ uint32_t pack2(unsigned short a, unsigned short b) {
    return (uint32_t)a | ((uint32_t)b << 16);
}

__device__ __forceinline__ void mma_bf16(float* d, const uint32_t* a, const uint32_t* b) {
    asm volatile(
        "mma.sync.aligned.m16n8k16.row.col.f32.bf16.bf16.f32 "
        "{%0,%1,%2,%3}, {%4,%5,%6,%7}, {%8,%9}, {%0,%1,%2,%3};"
        : "+f"(d[0]), "+f"(d[1]), "+f"(d[2]), "+f"(d[3])
        : "r"(a[0]), "r"(a[1]), "r"(a[2]), "r"(a[3]), "r"(b[0]), "r"(b[1]));
}
#define LDMX4(r, addr) \
    asm volatile("ldmatrix.sync.aligned.m8n8.x4.shared.b16 {%0,%1,%2,%3}, [%4];" \
        : "=r"((r)[0]), "=r"((r)[1]), "=r"((r)[2]), "=r"((r)[3]) : "r"(addr))
#define CP16(dst, src) \
    asm volatile("cp.async.cg.shared.global [%0], [%1], 16;" :: "r"(dst), "l"(src) : "memory")
#define CPCOMMIT() asm volatile("cp.async.commit_group;" ::: "memory")
#define CPWAIT1()  asm volatile("cp.async.wait_group 1;" ::: "memory")
#define CPWAIT0()  asm volatile("cp.async.wait_group 0;" ::: "memory")

// ---------------------------------------------------------------------------
// Weight prep
// ---------------------------------------------------------------------------
__global__ void prep_w(const float* __restrict__ W0, const float* __restrict__ W1,
                       const float* __restrict__ W2,
                       unsigned short* __restrict__ bh, unsigned short* __restrict__ bl)
{
    int idx = blockIdx.x * blockDim.x + threadIdx.x;
    if (idx >= WT_TOTAL) return;
    const float* W; int K, base;
    if (idx < 4 * WCH)       { W = W0; K = 128; base = 0; }
    else if (idx < 12 * WCH) { W = W1; K = 256; base = 4 * WCH; }
    else                     { W = W2; K = 256; base = 12 * WCH; }
    int e = idx - base;
    int chunk = e >> 13;
    int rem   = e & 8191;
    int n  = rem >> 5;
    int kk = rem & 31;
    int h = n >> 5, o = n & 31;
    int k = chunk * 32 + kk;
    float v = W[((size_t)h * K + k) * 32 + o];
    unsigned short hi = f2bf(v);
    bh[idx] = hi;
    bl[idx] = f2bf(v - bf2f(hi));
}

// ---------------------------------------------------------------------------
// split_x
// ---------------------------------------------------------------------------
__global__ void split_x(const float* __restrict__ x,
                        unsigned short* __restrict__ ah, unsigned short* __restrict__ al)
{
    int i = blockIdx.x * blockDim.x + threadIdx.x;
    if (i * 4 >= N_NODES * 128) return;
    float4 v = *(const float4*)(x + i * 4);
    unsigned short hx = f2bf(v.x), hy = f2bf(v.y), hz = f2bf(v.z), hw = f2bf(v.w);
    uint2 hp, lp;
    hp.x = pack2(hx, hy); hp.y = pack2(hz, hw);
    lp.x = pack2(f2bf(v.x - bf2f(hx)), f2bf(v.y - bf2f(hy)));
    lp.y = pack2(f2bf(v.z - bf2f(hz)), f2bf(v.w - bf2f(hw)));
    *(uint2*)(ah + i * 4) = hp;
    *(uint2*)(al + i * 4) = lp;
}

// ---------------------------------------------------------------------------
// bf16 3-term split GEMM: CTA 128x256 (full N), 512 threads, 16 warps 2m x 8n,
// warp tile 64x32 (identical per-warp shape to R8). BK=32, 2-stage cp.async.
// A loaded ONCE per row tile; B staged once per CTA.
// smem/stage: Ah(10240) Al(10240) Bh(20480) Bl(20480) = 61440; 2 stages.
// ---------------------------------------------------------------------------
#define SROW 80
#define STG 61440
#define SMEM_BYTES (2 * STG)

__global__ __launch_bounds__(512, 1)
void gemm_mma(const unsigned short* __restrict__ Ah, const unsigned short* __restrict__ Al,
              const unsigned short* __restrict__ wbh, const unsigned short* __restrict__ wbl,
              const float* __restrict__ bias, float* __restrict__ C,
              unsigned short* __restrict__ NBH, int K, int wbase)
{
    extern __shared__ char smem[];
    const uint32_t sbase = (uint32_t)__cvta_generic_to_shared(smem);

    const int tid  = threadIdx.x;
    const int wid  = tid >> 5;
    const int lane = tid & 31;
    const int g    = lane >> 2;
    const int t4   = lane & 3;
    const int wm   = wid & 1;        // 0..1  -> 64-row slot
    const int wn   = wid >> 1;       // 0..7  -> 32-col slot
    const int row0 = blockIdx.x * 128;
    const int nch  = K >> 5;

    const uint32_t aro = ((((lane >> 3) & 1) * 8 + (lane & 7)) * SROW) + ((lane >> 4) * 16);
    const uint32_t bro = ((((lane >> 4) & 1) * 8 + (lane & 7)) * SROW) + (((lane >> 3) & 1) * 16);

    auto fill = [&](int s, int c) {
        uint32_t st = sbase + s * STG;
        const unsigned short* srcB  = wbh + wbase + c * WCH;
        const unsigned short* srcBl = wbl + wbase + c * WCH;
        // A: 128 rows x 4 segs = 512 slots -> 1 per thread (hi + lo)
        {
            int row = tid >> 2, seg = tid & 3;
            size_t aoff = (size_t)(row0 + row) * K + c * 32 + seg * 8;
            uint32_t d = st + row * SROW + seg * 16;
            CP16(d,         Ah + aoff);
            CP16(d + 10240, Al + aoff);
        }
        // B: 256 rows x 4 segs = 1024 slots -> 2 per thread (hi + lo)
#pragma unroll
        for (int i = 0; i < 2; i++) {
            int j = tid + i * 512;
            int row = j >> 2, seg = j & 3;
            size_t boff = (size_t)row * 32 + seg * 8;
            uint32_t d = st + 20480 + row * SROW + seg * 16;
            CP16(d,         srcB  + boff);
            CP16(d + 20480, srcBl + boff);
        }
    };

    float acc[4][4][4];
#pragma unroll
    for (int i = 0; i < 4; i++)
#pragma unroll
        for (int j = 0; j < 4; j++)
#pragma unroll
            for (int q = 0; q < 4; q++) acc[i][j][q] = 0.0f;

    fill(0, 0);
    CPCOMMIT();

    for (int c = 0; c < nch; c++) {
        int s = c & 1;
        if (c + 1 < nch) { fill(s ^ 1, c + 1); CPCOMMIT(); CPWAIT1(); }
        else             { CPWAIT0(); }
        __syncthreads();

        uint32_t stAh = sbase + s * STG + (wm * 64) * SROW + aro;
        uint32_t stAl = stAh + 10240;
        uint32_t stBh = sbase + s * STG + 20480 + (wn * 32) * SROW + bro;
        uint32_t stBl = stBh + 20480;

#pragma unroll
        for (int k16 = 0; k16 < 2; k16++) {
            uint32_t ko = k16 * 32;
            uint32_t ah[4][4], al[4][4], bh4[2][4], bl4[2][4];
#pragma unroll
            for (int ma = 0; ma < 4; ma++) {
                LDMX4(ah[ma], stAh + ma * 16 * SROW + ko);
                LDMX4(al[ma], stAl + ma * 16 * SROW + ko);
            }
#pragma unroll
            for (int np = 0; np < 2; np++) {
                LDMX4(bh4[np], stBh + np * 16 * SROW + ko);
                LDMX4(bl4[np], stBl + np * 16 * SROW + ko);
            }
#pragma unroll
            for (int na = 0; na < 4; na++) {
                uint32_t bhf[2] = { bh4[na >> 1][(na & 1) * 2], bh4[na >> 1][(na & 1) * 2 + 1] };
                uint32_t blf[2] = { bl4[na >> 1][(na & 1) * 2], bl4[na >> 1][(na & 1) * 2 + 1] };
#pragma unroll
                for (int ma = 0; ma < 4; ma++) {
                    mma_bf16(acc[ma][na], ah[ma], bhf);
                    mma_bf16(acc[ma][na], ah[ma], blf);
                    mma_bf16(acc[ma][na], al[ma], bhf);
                }
            }
        }
        __syncthreads();
    }

    // epilogue
#pragma unroll
    for (int ma = 0; ma < 4; ma++) {
#pragma unroll
        for (int na = 0; na < 4; na++) {
            int cg = wn * 32 + na * 8 + t4 * 2;
            float bx = __ldg(&bias[cg]);
            float by = __ldg(&bias[cg + 1]);
            int r1 = row0 + wm * 64 + ma * 16 + g;
            int r2 = r1 + 8;
            if (r1 < N_NODES) {
                float2 v = make_float2(acc[ma][na][0] + bx, acc[ma][na][1] + by);
                if (r1 == 0) v = make_float2(NEG_BIG, NEG_BIG);
                *(float2*)(C + (size_t)r1 * HD + cg) = v;
                *(uint32_t*)(NBH + (size_t)r1 * HD + cg) = pack2(f2bf(v.x), f2bf(v.y));
            }
            if (r2 < N_NODES) {
                float2 v = make_float2(acc[ma][na][2] + bx, acc[ma][na][3] + by);
                *(float2*)(C + (size_t)r2 * HD + cg) = v;
                *(uint32_t*)(NBH + (size_t)r2 * HD + cg) = pack2(f2bf(v.x), f2bf(v.y));
            }
        }
    }
}

// ---------------------------------------------------------------------------
// Attention (unchanged R8 best)
// ---------------------------------------------------------------------------
__global__ __launch_bounds__(256)
void attn_kernel(const float* __restrict__ H, const unsigned short* __restrict__ NBH,
                 const int* __restrict__ a2a32,
                 unsigned short* __restrict__ outh, unsigned short* __restrict__ outl,
                 float* __restrict__ outf)
{
    const int gwarp = (blockIdx.x * blockDim.x + threadIdx.x) >> 5;
    if (gwarp >= N_NODES) return;
    const int node = gwarp;
    const int lane = threadIdx.x & 31;
    const int head = lane >> 2;
    const int part = lane & 3;

    const bool idx64 = ((a2a32[1] | a2a32[3] | a2a32[5] | a2a32[7]) == 0);

    const int off = head * 32 + part * 8;
    const uint32_t offb = (uint32_t)off * 2;

    uint32_t nofs[N_NBRS];
    if (!idx64) {
        const int4* p = (const int4*)(a2a32 + node * N_NBRS);
        int4 q0 = p[0], q1 = p[1], q2 = p[2];
        nofs[0] = ((uint32_t)q0.x << 9) + offb; nofs[1]  = ((uint32_t)q0.y << 9) + offb;
        nofs[2] = ((uint32_t)q0.z << 9) + offb; nofs[3]  = ((uint32_t)q0.w << 9) + offb;
        nofs[4] = ((uint32_t)q1.x << 9) + offb; nofs[5]  = ((uint32_t)q1.y << 9) + offb;
        nofs[6] = ((uint32_t)q1.z << 9) + offb; nofs[7]  = ((uint32_t)q1.w << 9) + offb;
        nofs[8] = ((uint32_t)q2.x << 9) + offb; nofs[9]  = ((uint32_t)q2.y << 9) + offb;
        nofs[10] = ((uint32_t)q2.z << 9) + offb; nofs[11] = ((uint32_t)q2.w << 9) + offb;
    } else {
#pragma unroll
        for (int k = 0; k < N_NBRS; k++)
            nofs[k] = ((uint32_t)a2a32[2 * (node * N_NBRS + k)] << 9) + offb;
    }
    const char* nb = (const char*)NBH;

    const float* hrow = H + (size_t)node * HD + off;
    float4 u0 = *(const float4*)hrow;
    float4 u1 = *(const float4*)(hrow + 4);
    float hn[8] = {u0.x, u0.y, u0.z, u0.w, u1.x, u1.y, u1.z, u1.w};

    float s = 0.f;
#pragma unroll
    for (int i = 0; i < 8; i++) s = fmaf(hn[i], hn[i], s);
    s += __shfl_xor_sync(0xffffffffu, s, 1);
    s += __shfl_xor_sync(0xffffffffu, s, 2);
    const float s0 = s;

    float d[N_NBRS];
#pragma unroll
    for (int half = 0; half < 2; half++) {
        uint4 p[6];
#pragma unroll
        for (int j = 0; j < 6; j++)
            p[j] = *(const uint4*)(nb + nofs[half * 6 + j]);
#pragma unroll
        for (int j = 0; j < 6; j++) {
            uint32_t w0 = p[j].x, w1 = p[j].y, w2 = p[j].z, w3 = p[j].w;
            float dd;
            dd = hn[0] * __uint_as_float(w0 << 16);
            dd = fmaf(hn[1], __uint_as_float(w0 & 0xffff0000u), dd);
            dd = fmaf(hn[2], __uint_as_float(w1 << 16), dd);
            dd = fmaf(hn[3], __uint_as_float(w1 & 0xffff0000u), dd);
            dd = fmaf(hn[4], __uint_as_float(w2 << 16), dd);
            dd = fmaf(hn[5], __uint_as_float(w2 & 0xffff0000u), dd);
            dd = fmaf(hn[6], __uint_as_float(w3 << 16), dd);
            dd = fmaf(hn[7], __uint_as_float(w3 & 0xffff0000u), dd);
            dd += __shfl_xor_sync(0xffffffffu, dd, 1);
            dd += __shfl_xor_sync(0xffffffffu, dd, 2);
            d[half * 6 + j] = dd;
        }
    }

    float denom = 1.0f;
#pragma unroll
    for (int k = 0; k < N_NBRS; k++) denom += __expf(d[k] - s0);

    float attn0 = __fdividef(1.0f, denom);
    if (node == 0) attn0 = 0.0f;

    float v[8];
#pragma unroll
    for (int i = 0; i < 8; i++) v[i] = hn[i] * attn0;

    if (outf) {
        float* orow = outf + (size_t)node * HD + off;
        *(float4*)orow       = make_float4(v[0], v[1], v[2], v[3]);
        *(float4*)(orow + 4) = make_float4(v[4], v[5], v[6], v[7]);
    } else {
        unsigned short hh[8];
        uint4 hp, lp;
#pragma unroll
        for (int i = 0; i < 8; i++) hh[i] = f2bf(v[i]);
        hp.x = pack2(hh[0], hh[1]); hp.y = pack2(hh[2], hh[3]);
        hp.z = pack2(hh[4], hh[5]); hp.w = pack2(hh[6], hh[7]);
        lp.x = pack2(f2bf(v[0] - bf2f(hh[0])), f2bf(v[1] - bf2f(hh[1])));
        lp.y = pack2(f2bf(v[2] - bf2f(hh[2])), f2bf(v[3] - bf2f(hh[3])));
        lp.z = pack2(f2bf(v[4] - bf2f(hh[4])), f2bf(v[5] - bf2f(hh[5])));
        lp.w = pack2(f2bf(v[6] - bf2f(hh[6])), f2bf(v[7] - bf2f(hh[7])));
        *(uint4*)(outh + (size_t)node * HD + off) = hp;
        *(uint4*)(outl + (size_t)node * HD + off) = lp;
    }
}

// ---------------------------------------------------------------------------
// Readout
// ---------------------------------------------------------------------------
__global__ __launch_bounds__(256)
void readout_kernel(const float* __restrict__ node_repr,
                    const float* __restrict__ Wo1, const float* __restrict__ bo1,
                    const float* __restrict__ Wo2, const float* __restrict__ bo2,
                    float* __restrict__ graph_repr, float* __restrict__ y)
{
    __shared__ float g[HD];
    const int gi = blockIdx.x;
    const int c  = threadIdx.x;

    float ssum = 0.f;
    const float* base = node_repr + (size_t)(1 + gi * 50) * HD + c;
#pragma unroll 10
    for (int r = 0; r < 50; r++) ssum += base[(size_t)r * HD];
    g[c] = ssum;
    graph_repr[(size_t)gi * HD + c] = ssum;
    __syncthreads();

    if (c < 32) {
        float acc = bo1[c];
#pragma unroll 8
        for (int d = 0; d < HD; d++) acc = fmaf(g[d], Wo1[d * 32 + c], acc);
        acc = fmaxf(acc, 0.0f);
        float val = acc * Wo2[c];
#pragma unroll
        for (int o = 16; o > 0; o >>= 1)
            val += __shfl_xor_sync(0xffffffffu, val, o);
        if (c == 0) y[gi] = val + bo2[0];
    }
}

// ---------------------------------------------------------------------------
extern "C" void kernel_launch(void* const* d_in, const int* in_sizes, int n_in,
                              void* d_out, int out_size)
{
    const float* x   = (const float*)d_in[0];
    const int*   a2a = (const int*)d_in[1];
    const float* W0  = (const float*)d_in[3];
    const float* b0  = (const float*)d_in[4];
    const float* W1  = (const float*)d_in[5];
    const float* b1  = (const float*)d_in[6];
    const float* W2  = (const float*)d_in[7];
    const float* b2  = (const float*)d_in[8];
    const float* Wo1 = (const float*)d_in[9];
    const float* bo1 = (const float*)d_in[10];
    const float* Wo2 = (const float*)d_in[11];
    const float* bo2 = (const float*)d_in[12];

    float* out        = (float*)d_out;
    float* node_repr  = out;
    float* graph_repr = out + (size_t)N_NODES * HD;
    float* y          = graph_repr + (size_t)N_GRAPHS * HD;

    float* bufH = nullptr;
    unsigned short *nbh = nullptr, *ah = nullptr, *al = nullptr, *wbh = nullptr, *wbl = nullptr;
    cudaGetSymbolAddress((void**)&bufH, g_bufH);
    cudaGetSymbolAddress((void**)&nbh, g_nbh);
    cudaGetSymbolAddress((void**)&ah, g_ah);
    cudaGetSymbolAddress((void**)&al, g_al);
    cudaGetSymbolAddress((void**)&wbh, g_wbh);
    cudaGetSymbolAddress((void**)&wbl, g_wbl);

    cudaFuncSetAttribute(gemm_mma, cudaFuncAttributeMaxDynamicSharedMemorySize, SMEM_BYTES);

    const int ggrid     = N_ROW_TILES;             // 391 full-N tiles
    const int attn_grid = (N_NODES + 7) / 8;

    prep_w<<<(WT_TOTAL + 255) / 256, 256>>>(W0, W1, W2, wbh, wbl);
    split_x<<<(N_NODES * 128 / 4 + 255) / 256, 256>>>(x, ah, al);

    gemm_mma<<<ggrid, 512, SMEM_BYTES>>>(ah, al, wbh, wbl, b0, bufH, nbh, 128, 0);
    attn_kernel<<<attn_grid, 256>>>(bufH, nbh, a2a, ah, al, nullptr);
    gemm_mma<<<ggrid, 512, SMEM_BYTES>>>(ah, al, wbh, wbl, b1, bufH, nbh, 256, 4 * WCH);
    attn_kernel<<<attn_grid, 256>>>(bufH, nbh, a2a, ah, al, nullptr);
    gemm_mma<<<ggrid, 512, SMEM_BYTES>>>(ah, al, wbh, wbl, b2, bufH, nbh, 256, 12 * WCH);
    attn_kernel<<<attn_grid, 256>>>(bufH, nbh, a2a, nullptr, nullptr, node_repr);

    readout_kernel<<<N_GRAPHS, 256>>>(node_repr, Wo1, bo1, Wo2, bo2, graph_repr, y);
}

// round 14
// speedup vs baseline: 1.0782x; 1.0782x over previous
#include <cuda_runtime.h>
#include <cuda_bf16.h>
#include <math.h>
#include <stdint.h>

#define N_NODES   50001
#define N_PAD     (N_NODES + 128)
#define N_NBRS    12
#define N_GRAPHS  1000
#define NEG_BIG   (-9000000000000000.0f)
#define HD        256

// ---------------------------------------------------------------------------
// Scratch: GEMM output stored as bf16 hi/lo pair (no fp32 copy).
// g_hh doubles as the neighbor-gather table.
// ---------------------------------------------------------------------------
__device__ unsigned short g_hh[(size_t)N_PAD * HD];             // layer out hi
__device__ unsigned short g_hl[(size_t)N_PAD * HD];             // layer out lo
__device__ unsigned short g_ah[(size_t)N_PAD * HD];             // next-layer A hi
__device__ unsigned short g_al[(size_t)N_PAD * HD];             // next-layer A lo

#define WCH 8192                          // 256*32
#define WT_TOTAL (20 * WCH)
__device__ unsigned short g_wbh[WT_TOTAL];
__device__ unsigned short g_wbl[WT_TOTAL];

// ---------------------------------------------------------------------------
// helpers
// ---------------------------------------------------------------------------
__device__ __forceinline__ unsigned short f2bf(float v) {
    return __bfloat16_as_ushort(__float2bfloat16_rn(v));
}
__device__ __forceinline__ float bf2f(unsigned short u) {
    return __bfloat162float(__ushort_as_bfloat16(u));
}
__device__ __forceinline__ uint32_t pack2(unsigned short a, unsigned short b) {
    return (uint32_t)a | ((uint32_t)b << 16);
}

__device__ __forceinline__ void mma_bf16(float* d, const uint32_t* a, const uint32_t* b) {
    asm volatile(
        "mma.sync.aligned.m16n8k16.row.col.f32.bf16.bf16.f32 "
        "{%0,%1,%2,%3}, {%4,%5,%6,%7}, {%8,%9}, {%0,%1,%2,%3};"
        : "+f"(d[0]), "+f"(d[1]), "+f"(d[2]), "+f"(d[3])
        : "r"(a[0]), "r"(a[1]), "r"(a[2]), "r"(a[3]), "r"(b[0]), "r"(b[1]));
}
#define LDMX4(r, addr) \
    asm volatile("ldmatrix.sync.aligned.m8n8.x4.shared.b16 {%0,%1,%2,%3}, [%4];" \
        : "=r"((r)[0]), "=r"((r)[1]), "=r"((r)[2]), "=r"((r)[3]) : "r"(addr))
#define CP16(dst, src) \
    asm volatile("cp.async.cg.shared.global [%0], [%1], 16;" :: "r"(dst), "l"(src) : "memory")
#define CPCOMMIT() asm volatile("cp.async.commit_group;" ::: "memory")
#define CPWAIT1()  asm volatile("cp.async.wait_group 1;" ::: "memory")
#define CPWAIT0()  asm volatile("cp.async.wait_group 0;" ::: "memory")

// ---------------------------------------------------------------------------
// Weight prep
// ---------------------------------------------------------------------------
__global__ void prep_w(const float* __restrict__ W0, const float* __restrict__ W1,
                       const float* __restrict__ W2,
                       unsigned short* __restrict__ bh, unsigned short* __restrict__ bl)
{
    int idx = blockIdx.x * blockDim.x + threadIdx.x;
    if (idx >= WT_TOTAL) return;
    const float* W; int K, base;
    if (idx < 4 * WCH)       { W = W0; K = 128; base = 0; }
    else if (idx < 12 * WCH) { W = W1; K = 256; base = 4 * WCH; }
    else                     { W = W2; K = 256; base = 12 * WCH; }
    int e = idx - base;
    int chunk = e >> 13;
    int rem   = e & 8191;
    int n  = rem >> 5;
    int kk = rem & 31;
    int h = n >> 5, o = n & 31;
    int k = chunk * 32 + kk;
    float v = W[((size_t)h * K + k) * 32 + o];
    unsigned short hi = f2bf(v);
    bh[idx] = hi;
    bl[idx] = f2bf(v - bf2f(hi));
}

// ---------------------------------------------------------------------------
// split_x
// ---------------------------------------------------------------------------
__global__ void split_x(const float* __restrict__ x,
                        unsigned short* __restrict__ ah, unsigned short* __restrict__ al)
{
    int i = blockIdx.x * blockDim.x + threadIdx.x;
    if (i * 4 >= N_NODES * 128) return;
    float4 v = *(const float4*)(x + i * 4);
    unsigned short hx = f2bf(v.x), hy = f2bf(v.y), hz = f2bf(v.z), hw = f2bf(v.w);
    uint2 hp, lp;
    hp.x = pack2(hx, hy); hp.y = pack2(hz, hw);
    lp.x = pack2(f2bf(v.x - bf2f(hx)), f2bf(v.y - bf2f(hy)));
    lp.y = pack2(f2bf(v.z - bf2f(hz)), f2bf(v.w - bf2f(hw)));
    *(uint2*)(ah + i * 4) = hp;
    *(uint2*)(al + i * 4) = lp;
}

// ---------------------------------------------------------------------------
// GEMM — EXACT R8 winner structure; epilogue stores bf16 hi/lo only.
// CTA 128x128, 8 warps (2m x 4n), warp 64x32, BK=32, 2-stage cp.async.
// ---------------------------------------------------------------------------
#define SROW 80
#define SARR 10240
#define SMEM_BYTES (8 * SARR)

__global__ __launch_bounds__(256, 2)
void gemm_mma(const unsigned short* __restrict__ Ah, const unsigned short* __restrict__ Al,
              const unsigned short* __restrict__ wbh, const unsigned short* __restrict__ wbl,
              const float* __restrict__ bias,
              unsigned short* __restrict__ Hh, unsigned short* __restrict__ Hl,
              int K, int wbase)
{
    extern __shared__ char smem[];
    const uint32_t sbase = (uint32_t)__cvta_generic_to_shared(smem);

    const int tid  = threadIdx.x;
    const int wid  = tid >> 5;
    const int lane = tid & 31;
    const int g    = lane >> 2;
    const int t4   = lane & 3;
    const int wm   = wid & 1;
    const int wn   = wid >> 1;
    const int row0 = blockIdx.x * 128;
    const int col0 = blockIdx.y * 128;
    const int nch  = K >> 5;

    const int r_a  = tid >> 2, seg_a = tid & 3;

    const uint32_t aro = ((((lane >> 3) & 1) * 8 + (lane & 7)) * SROW) + ((lane >> 4) * 16);
    const uint32_t bro = ((((lane >> 4) & 1) * 8 + (lane & 7)) * SROW) + (((lane >> 3) & 1) * 16);

    auto fill = [&](int s, int c) {
        uint32_t stA = sbase + (s * 4) * SARR;
        uint32_t stB = sbase + (s * 4 + 2) * SARR;
        const unsigned short* srcB  = wbh + wbase + c * WCH + (col0 << 5);
        const unsigned short* srcBl = wbl + wbase + c * WCH + (col0 << 5);
#pragma unroll
        for (int i = 0; i < 2; i++) {
            int row = r_a + i * 64, seg = seg_a;
            size_t aoff = (size_t)(row0 + row) * K + c * 32 + seg * 8;
            uint32_t d = stA + row * SROW + seg * 16;
            CP16(d,        Ah + aoff);
            CP16(d + SARR, Al + aoff);
            size_t boff = (size_t)row * 32 + seg * 8;
            uint32_t db = stB + row * SROW + seg * 16;
            CP16(db,        srcB  + boff);
            CP16(db + SARR, srcBl + boff);
        }
    };

    float acc[4][4][4];
#pragma unroll
    for (int i = 0; i < 4; i++)
#pragma unroll
        for (int j = 0; j < 4; j++)
#pragma unroll
            for (int q = 0; q < 4; q++) acc[i][j][q] = 0.0f;

    fill(0, 0);
    CPCOMMIT();

    for (int c = 0; c < nch; c++) {
        int s = c & 1;
        if (c + 1 < nch) { fill(s ^ 1, c + 1); CPCOMMIT(); CPWAIT1(); }
        else             { CPWAIT0(); }
        __syncthreads();

        uint32_t stAh = sbase + (s * 4) * SARR + (wm * 64) * SROW + aro;
        uint32_t stAl = stAh + SARR;
        uint32_t stBh = sbase + (s * 4 + 2) * SARR + (wn * 32) * SROW + bro;
        uint32_t stBl = stBh + SARR;

#pragma unroll
        for (int k16 = 0; k16 < 2; k16++) {
            uint32_t ko = k16 * 32;
            uint32_t ah[4][4], al[4][4], bh4[2][4], bl4[2][4];
#pragma unroll
            for (int ma = 0; ma < 4; ma++) {
                LDMX4(ah[ma], stAh + ma * 16 * SROW + ko);
                LDMX4(al[ma], stAl + ma * 16 * SROW + ko);
            }
#pragma unroll
            for (int np = 0; np < 2; np++) {
                LDMX4(bh4[np], stBh + np * 16 * SROW + ko);
                LDMX4(bl4[np], stBl + np * 16 * SROW + ko);
            }
#pragma unroll
            for (int na = 0; na < 4; na++) {
                uint32_t bhf[2] = { bh4[na >> 1][(na & 1) * 2], bh4[na >> 1][(na & 1) * 2 + 1] };
                uint32_t blf[2] = { bl4[na >> 1][(na & 1) * 2], bl4[na >> 1][(na & 1) * 2 + 1] };
#pragma unroll
                for (int ma = 0; ma < 4; ma++) {
                    mma_bf16(acc[ma][na], ah[ma], bhf);
                    mma_bf16(acc[ma][na], ah[ma], blf);
                    mma_bf16(acc[ma][na], al[ma], bhf);
                }
            }
        }
        __syncthreads();
    }

    // epilogue: bias, row0 -> NEG_BIG; store bf16 hi + lo pairs only
#pragma unroll
    for (int ma = 0; ma < 4; ma++) {
#pragma unroll
        for (int na = 0; na < 4; na++) {
            int cg = col0 + wn * 32 + na * 8 + t4 * 2;
            float bx = __ldg(&bias[cg]);
            float by = __ldg(&bias[cg + 1]);
            int r1 = row0 + wm * 64 + ma * 16 + g;
            int r2 = r1 + 8;
#pragma unroll
            for (int rr = 0; rr < 2; rr++) {
                int r = rr ? r2 : r1;
                if (r >= N_NODES) continue;
                float vx = acc[ma][na][rr * 2 + 0] + bx;
                float vy = acc[ma][na][rr * 2 + 1] + by;
                if (r == 0) { vx = NEG_BIG; vy = NEG_BIG; }
                unsigned short hx = f2bf(vx), hy = f2bf(vy);
                *(uint32_t*)(Hh + (size_t)r * HD + cg) = pack2(hx, hy);
                *(uint32_t*)(Hl + (size_t)r * HD + cg) =
                    pack2(f2bf(vx - bf2f(hx)), f2bf(vy - bf2f(hy)));
            }
        }
    }
}

// ---------------------------------------------------------------------------
// Attention: own row reconstructed from bf16 hi+lo; neighbors from hi.
// ---------------------------------------------------------------------------
__global__ __launch_bounds__(256)
void attn_kernel(const unsigned short* __restrict__ Hh, const unsigned short* __restrict__ Hl,
                 const int* __restrict__ a2a32,
                 unsigned short* __restrict__ outh, unsigned short* __restrict__ outl,
                 float* __restrict__ outf)
{
    const int gwarp = (blockIdx.x * blockDim.x + threadIdx.x) >> 5;
    if (gwarp >= N_NODES) return;
    const int node = gwarp;
    const int lane = threadIdx.x & 31;
    const int head = lane >> 2;
    const int part = lane & 3;

    const bool idx64 = ((a2a32[1] | a2a32[3] | a2a32[5] | a2a32[7]) == 0);

    const int off = head * 32 + part * 8;
    const uint32_t offb = (uint32_t)off * 2;

    uint32_t nofs[N_NBRS];
    if (!idx64) {
        const int4* p = (const int4*)(a2a32 + node * N_NBRS);
        int4 q0 = p[0], q1 = p[1], q2 = p[2];
        nofs[0] = ((uint32_t)q0.x << 9) + offb; nofs[1]  = ((uint32_t)q0.y << 9) + offb;
        nofs[2] = ((uint32_t)q0.z << 9) + offb; nofs[3]  = ((uint32_t)q0.w << 9) + offb;
        nofs[4] = ((uint32_t)q1.x << 9) + offb; nofs[5]  = ((uint32_t)q1.y << 9) + offb;
        nofs[6] = ((uint32_t)q1.z << 9) + offb; nofs[7]  = ((uint32_t)q1.w << 9) + offb;
        nofs[8] = ((uint32_t)q2.x << 9) + offb; nofs[9]  = ((uint32_t)q2.y << 9) + offb;
        nofs[10] = ((uint32_t)q2.z << 9) + offb; nofs[11] = ((uint32_t)q2.w << 9) + offb;
    } else {
#pragma unroll
        for (int k = 0; k < N_NBRS; k++)
            nofs[k] = ((uint32_t)a2a32[2 * (node * N_NBRS + k)] << 9) + offb;
    }
    const char* nb = (const char*)Hh;

    // own row: hi + lo reconstruct (one LDG.128 each)
    uint4 ph = *(const uint4*)(Hh + (size_t)node * HD + off);
    uint4 pl = *(const uint4*)(Hl + (size_t)node * HD + off);
    float hn[8];
    {
        uint32_t hw[4] = {ph.x, ph.y, ph.z, ph.w};
        uint32_t lw[4] = {pl.x, pl.y, pl.z, pl.w};
#pragma unroll
        for (int i = 0; i < 4; i++) {
            hn[2 * i]     = __uint_as_float(hw[i] << 16)        + __uint_as_float(lw[i] << 16);
            hn[2 * i + 1] = __uint_as_float(hw[i] & 0xffff0000u) + __uint_as_float(lw[i] & 0xffff0000u);
        }
    }

    float s = 0.f;
#pragma unroll
    for (int i = 0; i < 8; i++) s = fmaf(hn[i], hn[i], s);
    s += __shfl_xor_sync(0xffffffffu, s, 1);
    s += __shfl_xor_sync(0xffffffffu, s, 2);
    const float s0 = s;

    float d[N_NBRS];
#pragma unroll
    for (int half = 0; half < 2; half++) {
        uint4 p[6];
#pragma unroll
        for (int j = 0; j < 6; j++)
            p[j] = *(const uint4*)(nb + nofs[half * 6 + j]);
#pragma unroll
        for (int j = 0; j < 6; j++) {
            uint32_t w0 = p[j].x, w1 = p[j].y, w2 = p[j].z, w3 = p[j].w;
            float dd;
            dd = hn[0] * __uint_as_float(w0 << 16);
            dd = fmaf(hn[1], __uint_as_float(w0 & 0xffff0000u), dd);
            dd = fmaf(hn[2], __uint_as_float(w1 << 16), dd);
            dd = fmaf(hn[3], __uint_as_float(w1 & 0xffff0000u), dd);
            dd = fmaf(hn[4], __uint_as_float(w2 << 16), dd);
            dd = fmaf(hn[5], __uint_as_float(w2 & 0xffff0000u), dd);
            dd = fmaf(hn[6], __uint_as_float(w3 << 16), dd);
            dd = fmaf(hn[7], __uint_as_float(w3 & 0xffff0000u), dd);
            dd += __shfl_xor_sync(0xffffffffu, dd, 1);
            dd += __shfl_xor_sync(0xffffffffu, dd, 2);
            d[half * 6 + j] = dd;
        }
    }

    float denom = 1.0f;
#pragma unroll
    for (int k = 0; k < N_NBRS; k++) denom += __expf(d[k] - s0);

    float attn0 = __fdividef(1.0f, denom);
    if (node == 0) attn0 = 0.0f;

    float v[8];
#pragma unroll
    for (int i = 0; i < 8; i++) v[i] = hn[i] * attn0;

    if (outf) {
        float* orow = outf + (size_t)node * HD + off;
        *(float4*)orow       = make_float4(v[0], v[1], v[2], v[3]);
        *(float4*)(orow + 4) = make_float4(v[4], v[5], v[6], v[7]);
    } else {
        unsigned short hh[8];
        uint4 hp, lp;
#pragma unroll
        for (int i = 0; i < 8; i++) hh[i] = f2bf(v[i]);
        hp.x = pack2(hh[0], hh[1]); hp.y = pack2(hh[2], hh[3]);
        hp.z = pack2(hh[4], hh[5]); hp.w = pack2(hh[6], hh[7]);
        lp.x = pack2(f2bf(v[0] - bf2f(hh[0])), f2bf(v[1] - bf2f(hh[1])));
        lp.y = pack2(f2bf(v[2] - bf2f(hh[2])), f2bf(v[3] - bf2f(hh[3])));
        lp.z = pack2(f2bf(v[4] - bf2f(hh[4])), f2bf(v[5] - bf2f(hh[5])));
        lp.w = pack2(f2bf(v[6] - bf2f(hh[6])), f2bf(v[7] - bf2f(hh[7])));
        *(uint4*)(outh + (size_t)node * HD + off) = hp;
        *(uint4*)(outl + (size_t)node * HD + off) = lp;
    }
}

// ---------------------------------------------------------------------------
// Readout
// ---------------------------------------------------------------------------
__global__ __launch_bounds__(256)
void readout_kernel(const float* __restrict__ node_repr,
                    const float* __restrict__ Wo1, const float* __restrict__ bo1,
                    const float* __restrict__ Wo2, const float* __restrict__ bo2,
                    float* __restrict__ graph_repr, float* __restrict__ y)
{
    __shared__ float g[HD];
    const int gi = blockIdx.x;
    const int c  = threadIdx.x;

    float ssum = 0.f;
    const float* base = node_repr + (size_t)(1 + gi * 50) * HD + c;
#pragma unroll 10
    for (int r = 0; r < 50; r++) ssum += base[(size_t)r * HD];
    g[c] = ssum;
    graph_repr[(size_t)gi * HD + c] = ssum;
    __syncthreads();

    if (c < 32) {
        float acc = bo1[c];
#pragma unroll 8
        for (int d = 0; d < HD; d++) acc = fmaf(g[d], Wo1[d * 32 + c], acc);
        acc = fmaxf(acc, 0.0f);
        float val = acc * Wo2[c];
#pragma unroll
        for (int o = 16; o > 0; o >>= 1)
            val += __shfl_xor_sync(0xffffffffu, val, o);
        if (c == 0) y[gi] = val + bo2[0];
    }
}

// ---------------------------------------------------------------------------
extern "C" void kernel_launch(void* const* d_in, const int* in_sizes, int n_in,
                              void* d_out, int out_size)
{
    const float* x   = (const float*)d_in[0];
    const int*   a2a = (const int*)d_in[1];
    const float* W0  = (const float*)d_in[3];
    const float* b0  = (const float*)d_in[4];
    const float* W1  = (const float*)d_in[5];
    const float* b1  = (const float*)d_in[6];
    const float* W2  = (const float*)d_in[7];
    const float* b2  = (const float*)d_in[8];
    const float* Wo1 = (const float*)d_in[9];
    const float* bo1 = (const float*)d_in[10];
    const float* Wo2 = (const float*)d_in[11];
    const float* bo2 = (const float*)d_in[12];

    float* out        = (float*)d_out;
    float* node_repr  = out;
    float* graph_repr = out + (size_t)N_NODES * HD;
    float* y          = graph_repr + (size_t)N_GRAPHS * HD;

    unsigned short *hh = nullptr, *hl = nullptr, *ah = nullptr, *al = nullptr;
    unsigned short *wbh = nullptr, *wbl = nullptr;
    cudaGetSymbolAddress((void**)&hh, g_hh);
    cudaGetSymbolAddress((void**)&hl, g_hl);
    cudaGetSymbolAddress((void**)&ah, g_ah);
    cudaGetSymbolAddress((void**)&al, g_al);
    cudaGetSymbolAddress((void**)&wbh, g_wbh);
    cudaGetSymbolAddress((void**)&wbl, g_wbl);

    cudaFuncSetAttribute(gemm_mma, cudaFuncAttributeMaxDynamicSharedMemorySize, SMEM_BYTES);

    dim3 ggrid((N_NODES + 127) / 128, 2);          // exact R8 launch config
    const int attn_grid = (N_NODES + 7) / 8;

    prep_w<<<(WT_TOTAL + 255) / 256, 256>>>(W0, W1, W2, wbh, wbl);
    split_x<<<(N_NODES * 128 / 4 + 255) / 256, 256>>>(x, ah, al);

    gemm_mma<<<ggrid, 256, SMEM_BYTES>>>(ah, al, wbh, wbl, b0, hh, hl, 128, 0);
    attn_kernel<<<attn_grid, 256>>>(hh, hl, a2a, ah, al, nullptr);
    gemm_mma<<<ggrid, 256, SMEM_BYTES>>>(ah, al, wbh, wbl, b1, hh, hl, 256, 4 * WCH);
    attn_kernel<<<attn_grid, 256>>>(hh, hl, a2a, ah, al, nullptr);
    gemm_mma<<<ggrid, 256, SMEM_BYTES>>>(ah, al, wbh, wbl, b2, hh, hl, 256, 12 * WCH);
    attn_kernel<<<attn_grid, 256>>>(hh, hl, a2a, nullptr, nullptr, node_repr);

    readout_kernel<<<N_GRAPHS, 256>>>(node_repr, Wo1, bo1, Wo2, bo2, graph_repr, y);
}

// round 16
// speedup vs baseline: 1.1106x; 1.0301x over previous
#include <cuda_runtime.h>
#include <cuda_bf16.h>
#include <math.h>
#include <stdint.h>

#define N_NODES   50001
#define N_PAD     (N_NODES + 128)
#define N_NBRS    12
#define N_GRAPHS  1000
#define NEG_BIG   (-9000000000000000.0f)
#define HD        256

// ---------------------------------------------------------------------------
// Scratch: GEMM output stored as bf16 hi/lo pair. g_hh is the gather table.
// ---------------------------------------------------------------------------
__device__ unsigned short g_hh[(size_t)N_PAD * HD];
__device__ unsigned short g_hl[(size_t)N_PAD * HD];
__device__ unsigned short g_ah[(size_t)N_PAD * HD];
__device__ unsigned short g_al[(size_t)N_PAD * HD];

#define WCH 8192                          // 256*32
#define WT_TOTAL (20 * WCH)
__device__ unsigned short g_wbh[WT_TOTAL];
__device__ unsigned short g_wbl[WT_TOTAL];

// ---------------------------------------------------------------------------
// helpers
// ---------------------------------------------------------------------------
__device__ __forceinline__ unsigned short f2bf(float v) {
    return __bfloat16_as_ushort(__float2bfloat16_rn(v));
}
__device__ __forceinline__ float bf2f(unsigned short u) {
    return __bfloat162float(__ushort_as_bfloat16(u));
}
__device__ __forceinline__ uint32_t pack2(unsigned short a, unsigned short b) {
    return (uint32_t)a | ((uint32_t)b << 16);
}
__device__ __forceinline__ __nv_bfloat162 asbf2(uint32_t u) {
    __nv_bfloat162 r; memcpy(&r, &u, 4); return r;
}

__device__ __forceinline__ void mma_bf16(float* d, const uint32_t* a, const uint32_t* b) {
    asm volatile(
        "mma.sync.aligned.m16n8k16.row.col.f32.bf16.bf16.f32 "
        "{%0,%1,%2,%3}, {%4,%5,%6,%7}, {%8,%9}, {%0,%1,%2,%3};"
        : "+f"(d[0]), "+f"(d[1]), "+f"(d[2]), "+f"(d[3])
        : "r"(a[0]), "r"(a[1]), "r"(a[2]), "r"(a[3]), "r"(b[0]), "r"(b[1]));
}
#define LDMX4(r, addr) \
    asm volatile("ldmatrix.sync.aligned.m8n8.x4.shared.b16 {%0,%1,%2,%3}, [%4];" \
        : "=r"((r)[0]), "=r"((r)[1]), "=r"((r)[2]), "=r"((r)[3]) : "r"(addr))
#define CP16(dst, src) \
    asm volatile("cp.async.cg.shared.global [%0], [%1], 16;" :: "r"(dst), "l"(src) : "memory")
#define CPCOMMIT() asm volatile("cp.async.commit_group;" ::: "memory")
#define CPWAIT1()  asm volatile("cp.async.wait_group 1;" ::: "memory")
#define CPWAIT0()  asm volatile("cp.async.wait_group 0;" ::: "memory")

// ---------------------------------------------------------------------------
// Weight prep
// ---------------------------------------------------------------------------
__global__ void prep_w(const float* __restrict__ W0, const float* __restrict__ W1,
                       const float* __restrict__ W2,
                       unsigned short* __restrict__ bh, unsigned short* __restrict__ bl)
{
    int idx = blockIdx.x * blockDim.x + threadIdx.x;
    if (idx >= WT_TOTAL) return;
    const float* W; int K, base;
    if (idx < 4 * WCH)       { W = W0; K = 128; base = 0; }
    else if (idx < 12 * WCH) { W = W1; K = 256; base = 4 * WCH; }
    else                     { W = W2; K = 256; base = 12 * WCH; }
    int e = idx - base;
    int chunk = e >> 13;
    int rem   = e & 8191;
    int n  = rem >> 5;
    int kk = rem & 31;
    int h = n >> 5, o = n & 31;
    int k = chunk * 32 + kk;
    float v = W[((size_t)h * K + k) * 32 + o];
    unsigned short hi = f2bf(v);
    bh[idx] = hi;
    bl[idx] = f2bf(v - bf2f(hi));
}

// ---------------------------------------------------------------------------
// split_x
// ---------------------------------------------------------------------------
__global__ void split_x(const float* __restrict__ x,
                        unsigned short* __restrict__ ah, unsigned short* __restrict__ al)
{
    int i = blockIdx.x * blockDim.x + threadIdx.x;
    if (i * 4 >= N_NODES * 128) return;
    float4 v = *(const float4*)(x + i * 4);
    unsigned short hx = f2bf(v.x), hy = f2bf(v.y), hz = f2bf(v.z), hw = f2bf(v.w);
    uint2 hp, lp;
    hp.x = pack2(hx, hy); hp.y = pack2(hz, hw);
    lp.x = pack2(f2bf(v.x - bf2f(hx)), f2bf(v.y - bf2f(hy)));
    lp.y = pack2(f2bf(v.z - bf2f(hz)), f2bf(v.w - bf2f(hw)));
    *(uint2*)(ah + i * 4) = hp;
    *(uint2*)(al + i * 4) = lp;
}

// ---------------------------------------------------------------------------
// GEMM — R13 winner, unchanged.
// ---------------------------------------------------------------------------
#define SROW 80
#define SARR 10240
#define SMEM_BYTES (8 * SARR)

__global__ __launch_bounds__(256, 2)
void gemm_mma(const unsigned short* __restrict__ Ah, const unsigned short* __restrict__ Al,
              const unsigned short* __restrict__ wbh, const unsigned short* __restrict__ wbl,
              const float* __restrict__ bias,
              unsigned short* __restrict__ Hh, unsigned short* __restrict__ Hl,
              int K, int wbase)
{
    extern __shared__ char smem[];
    const uint32_t sbase = (uint32_t)__cvta_generic_to_shared(smem);

    const int tid  = threadIdx.x;
    const int wid  = tid >> 5;
    const int lane = tid & 31;
    const int g    = lane >> 2;
    const int t4   = lane & 3;
    const int wm   = wid & 1;
    const int wn   = wid >> 1;
    const int row0 = blockIdx.x * 128;
    const int col0 = blockIdx.y * 128;
    const int nch  = K >> 5;

    const int r_a  = tid >> 2, seg_a = tid & 3;

    const uint32_t aro = ((((lane >> 3) & 1) * 8 + (lane & 7)) * SROW) + ((lane >> 4) * 16);
    const uint32_t bro = ((((lane >> 4) & 1) * 8 + (lane & 7)) * SROW) + (((lane >> 3) & 1) * 16);

    auto fill = [&](int s, int c) {
        uint32_t stA = sbase + (s * 4) * SARR;
        uint32_t stB = sbase + (s * 4 + 2) * SARR;
        const unsigned short* srcB  = wbh + wbase + c * WCH + (col0 << 5);
        const unsigned short* srcBl = wbl + wbase + c * WCH + (col0 << 5);
#pragma unroll
        for (int i = 0; i < 2; i++) {
            int row = r_a + i * 64, seg = seg_a;
            size_t aoff = (size_t)(row0 + row) * K + c * 32 + seg * 8;
            uint32_t d = stA + row * SROW + seg * 16;
            CP16(d,        Ah + aoff);
            CP16(d + SARR, Al + aoff);
            size_t boff = (size_t)row * 32 + seg * 8;
            uint32_t db = stB + row * SROW + seg * 16;
            CP16(db,        srcB  + boff);
            CP16(db + SARR, srcBl + boff);
        }
    };

    float acc[4][4][4];
#pragma unroll
    for (int i = 0; i < 4; i++)
#pragma unroll
        for (int j = 0; j < 4; j++)
#pragma unroll
            for (int q = 0; q < 4; q++) acc[i][j][q] = 0.0f;

    fill(0, 0);
    CPCOMMIT();

    for (int c = 0; c < nch; c++) {
        int s = c & 1;
        if (c + 1 < nch) { fill(s ^ 1, c + 1); CPCOMMIT(); CPWAIT1(); }
        else             { CPWAIT0(); }
        __syncthreads();

        uint32_t stAh = sbase + (s * 4) * SARR + (wm * 64) * SROW + aro;
        uint32_t stAl = stAh + SARR;
        uint32_t stBh = sbase + (s * 4 + 2) * SARR + (wn * 32) * SROW + bro;
        uint32_t stBl = stBh + SARR;

#pragma unroll
        for (int k16 = 0; k16 < 2; k16++) {
            uint32_t ko = k16 * 32;
            uint32_t ah[4][4], al[4][4], bh4[2][4], bl4[2][4];
#pragma unroll
            for (int ma = 0; ma < 4; ma++) {
                LDMX4(ah[ma], stAh + ma * 16 * SROW + ko);
                LDMX4(al[ma], stAl + ma * 16 * SROW + ko);
            }
#pragma unroll
            for (int np = 0; np < 2; np++) {
                LDMX4(bh4[np], stBh + np * 16 * SROW + ko);
                LDMX4(bl4[np], stBl + np * 16 * SROW + ko);
            }
#pragma unroll
            for (int na = 0; na < 4; na++) {
                uint32_t bhf[2] = { bh4[na >> 1][(na & 1) * 2], bh4[na >> 1][(na & 1) * 2 + 1] };
                uint32_t blf[2] = { bl4[na >> 1][(na & 1) * 2], bl4[na >> 1][(na & 1) * 2 + 1] };
#pragma unroll
                for (int ma = 0; ma < 4; ma++) {
                    mma_bf16(acc[ma][na], ah[ma], bhf);
                    mma_bf16(acc[ma][na], ah[ma], blf);
                    mma_bf16(acc[ma][na], al[ma], bhf);
                }
            }
        }
        __syncthreads();
    }

#pragma unroll
    for (int ma = 0; ma < 4; ma++) {
#pragma unroll
        for (int na = 0; na < 4; na++) {
            int cg = col0 + wn * 32 + na * 8 + t4 * 2;
            float bx = __ldg(&bias[cg]);
            float by = __ldg(&bias[cg + 1]);
            int r1 = row0 + wm * 64 + ma * 16 + g;
            int r2 = r1 + 8;
#pragma unroll
            for (int rr = 0; rr < 2; rr++) {
                int r = rr ? r2 : r1;
                if (r >= N_NODES) continue;
                float vx = acc[ma][na][rr * 2 + 0] + bx;
                float vy = acc[ma][na][rr * 2 + 1] + by;
                if (r == 0) { vx = NEG_BIG; vy = NEG_BIG; }
                unsigned short hx = f2bf(vx), hy = f2bf(vy);
                *(uint32_t*)(Hh + (size_t)r * HD + cg) = pack2(hx, hy);
                *(uint32_t*)(Hl + (size_t)r * HD + cg) =
                    pack2(f2bf(vx - bf2f(hx)), f2bf(vy - bf2f(hy)));
            }
        }
    }
}

// ---------------------------------------------------------------------------
// Attention: neighbor dots via packed bf16x2 HFMA2 (own side = hi words).
// Own row value = hi+lo fp32 for s0/output. attn0 = 1/(1+sum exp(d-s0)).
// ---------------------------------------------------------------------------
__global__ __launch_bounds__(256)
void attn_kernel(const unsigned short* __restrict__ Hh, const unsigned short* __restrict__ Hl,
                 const int* __restrict__ a2a32,
                 unsigned short* __restrict__ outh, unsigned short* __restrict__ outl,
                 float* __restrict__ outf)
{
    const int gwarp = (blockIdx.x * blockDim.x + threadIdx.x) >> 5;
    if (gwarp >= N_NODES) return;
    const int node = gwarp;
    const int lane = threadIdx.x & 31;
    const int head = lane >> 2;
    const int part = lane & 3;

    const bool idx64 = ((a2a32[1] | a2a32[3] | a2a32[5] | a2a32[7]) == 0);

    const int off = head * 32 + part * 8;
    const uint32_t offb = (uint32_t)off * 2;

    uint32_t nofs[N_NBRS];
    if (!idx64) {
        const int4* p = (const int4*)(a2a32 + node * N_NBRS);
        int4 q0 = p[0], q1 = p[1], q2 = p[2];
        nofs[0] = ((uint32_t)q0.x << 9) + offb; nofs[1]  = ((uint32_t)q0.y << 9) + offb;
        nofs[2] = ((uint32_t)q0.z << 9) + offb; nofs[3]  = ((uint32_t)q0.w << 9) + offb;
        nofs[4] = ((uint32_t)q1.x << 9) + offb; nofs[5]  = ((uint32_t)q1.y << 9) + offb;
        nofs[6] = ((uint32_t)q1.z << 9) + offb; nofs[7]  = ((uint32_t)q1.w << 9) + offb;
        nofs[8] = ((uint32_t)q2.x << 9) + offb; nofs[9]  = ((uint32_t)q2.y << 9) + offb;
        nofs[10] = ((uint32_t)q2.z << 9) + offb; nofs[11] = ((uint32_t)q2.w << 9) + offb;
    } else {
#pragma unroll
        for (int k = 0; k < N_NBRS; k++)
            nofs[k] = ((uint32_t)a2a32[2 * (node * N_NBRS + k)] << 9) + offb;
    }
    const char* nb = (const char*)Hh;

    // own row: hi + lo reconstruct for fp32 path; hi words for packed dots
    uint4 ph = *(const uint4*)(Hh + (size_t)node * HD + off);
    uint4 pl = *(const uint4*)(Hl + (size_t)node * HD + off);
    float hn[8];
    {
        uint32_t hw[4] = {ph.x, ph.y, ph.z, ph.w};
        uint32_t lw[4] = {pl.x, pl.y, pl.z, pl.w};
#pragma unroll
        for (int i = 0; i < 4; i++) {
            hn[2 * i]     = __uint_as_float(hw[i] << 16)         + __uint_as_float(lw[i] << 16);
            hn[2 * i + 1] = __uint_as_float(hw[i] & 0xffff0000u) + __uint_as_float(lw[i] & 0xffff0000u);
        }
    }
    const __nv_bfloat162 a0 = asbf2(ph.x), a1 = asbf2(ph.y),
                         a2 = asbf2(ph.z), a3 = asbf2(ph.w);

    float s = 0.f;
#pragma unroll
    for (int i = 0; i < 8; i++) s = fmaf(hn[i], hn[i], s);
    s += __shfl_xor_sync(0xffffffffu, s, 1);
    s += __shfl_xor_sync(0xffffffffu, s, 2);
    const float s0 = s;

    float d[N_NBRS];
#pragma unroll
    for (int half = 0; half < 2; half++) {
        uint4 p[6];
#pragma unroll
        for (int j = 0; j < 6; j++)
            p[j] = *(const uint4*)(nb + nofs[half * 6 + j]);
#pragma unroll
        for (int j = 0; j < 6; j++) {
            __nv_bfloat162 acc2 = __hmul2(a0, asbf2(p[j].x));
            acc2 = __hfma2(a1, asbf2(p[j].y), acc2);
            acc2 = __hfma2(a2, asbf2(p[j].z), acc2);
            acc2 = __hfma2(a3, asbf2(p[j].w), acc2);
            float2 f = __bfloat1622float2(acc2);
            float dd = f.x + f.y;
            dd += __shfl_xor_sync(0xffffffffu, dd, 1);
            dd += __shfl_xor_sync(0xffffffffu, dd, 2);
            d[half * 6 + j] = dd;
        }
    }

    float denom = 1.0f;
#pragma unroll
    for (int k = 0; k < N_NBRS; k++) denom += __expf(d[k] - s0);

    float attn0 = __fdividef(1.0f, denom);
    if (node == 0) attn0 = 0.0f;

    float v[8];
#pragma unroll
    for (int i = 0; i < 8; i++) v[i] = hn[i] * attn0;

    if (outf) {
        float* orow = outf + (size_t)node * HD + off;
        *(float4*)orow       = make_float4(v[0], v[1], v[2], v[3]);
        *(float4*)(orow + 4) = make_float4(v[4], v[5], v[6], v[7]);
    } else {
        unsigned short hh[8];
        uint4 hp, lp;
#pragma unroll
        for (int i = 0; i < 8; i++) hh[i] = f2bf(v[i]);
        hp.x = pack2(hh[0], hh[1]); hp.y = pack2(hh[2], hh[3]);
        hp.z = pack2(hh[4], hh[5]); hp.w = pack2(hh[6], hh[7]);
        lp.x = pack2(f2bf(v[0] - bf2f(hh[0])), f2bf(v[1] - bf2f(hh[1])));
        lp.y = pack2(f2bf(v[2] - bf2f(hh[2])), f2bf(v[3] - bf2f(hh[3])));
        lp.z = pack2(f2bf(v[4] - bf2f(hh[4])), f2bf(v[5] - bf2f(hh[5])));
        lp.w = pack2(f2bf(v[6] - bf2f(hh[6])), f2bf(v[7] - bf2f(hh[7])));
        *(uint4*)(outh + (size_t)node * HD + off) = hp;
        *(uint4*)(outl + (size_t)node * HD + off) = lp;
    }
}

// ---------------------------------------------------------------------------
// Readout
// ---------------------------------------------------------------------------
__global__ __launch_bounds__(256)
void readout_kernel(const float* __restrict__ node_repr,
                    const float* __restrict__ Wo1, const float* __restrict__ bo1,
                    const float* __restrict__ Wo2, const float* __restrict__ bo2,
                    float* __restrict__ graph_repr, float* __restrict__ y)
{
    __shared__ float g[HD];
    const int gi = blockIdx.x;
    const int c  = threadIdx.x;

    float ssum = 0.f;
    const float* base = node_repr + (size_t)(1 + gi * 50) * HD + c;
#pragma unroll 10
    for (int r = 0; r < 50; r++) ssum += base[(size_t)r * HD];
    g[c] = ssum;
    graph_repr[(size_t)gi * HD + c] = ssum;
    __syncthreads();

    if (c < 32) {
        float acc = bo1[c];
#pragma unroll 8
        for (int d = 0; d < HD; d++) acc = fmaf(g[d], Wo1[d * 32 + c], acc);
        acc = fmaxf(acc, 0.0f);
        float val = acc * Wo2[c];
#pragma unroll
        for (int o = 16; o > 0; o >>= 1)
            val += __shfl_xor_sync(0xffffffffu, val, o);
        if (c == 0) y[gi] = val + bo2[0];
    }
}

// ---------------------------------------------------------------------------
extern "C" void kernel_launch(void* const* d_in, const int* in_sizes, int n_in,
                              void* d_out, int out_size)
{
    const float* x   = (const float*)d_in[0];
    const int*   a2a = (const int*)d_in[1];
    const float* W0  = (const float*)d_in[3];
    const float* b0  = (const float*)d_in[4];
    const float* W1  = (const float*)d_in[5];
    const float* b1  = (const float*)d_in[6];
    const float* W2  = (const float*)d_in[7];
    const float* b2  = (const float*)d_in[8];
    const float* Wo1 = (const float*)d_in[9];
    const float* bo1 = (const float*)d_in[10];
    const float* Wo2 = (const float*)d_in[11];
    const float* bo2 = (const float*)d_in[12];

    float* out        = (float*)d_out;
    float* node_repr  = out;
    float* graph_repr = out + (size_t)N_NODES * HD;
    float* y          = graph_repr + (size_t)N_GRAPHS * HD;

    unsigned short *hh = nullptr, *hl = nullptr, *ah = nullptr, *al = nullptr;
    unsigned short *wbh = nullptr, *wbl = nullptr;
    cudaGetSymbolAddress((void**)&hh, g_hh);
    cudaGetSymbolAddress((void**)&hl, g_hl);
    cudaGetSymbolAddress((void**)&ah, g_ah);
    cudaGetSymbolAddress((void**)&al, g_al);
    cudaGetSymbolAddress((void**)&wbh, g_wbh);
    cudaGetSymbolAddress((void**)&wbl, g_wbl);

    cudaFuncSetAttribute(gemm_mma, cudaFuncAttributeMaxDynamicSharedMemorySize, SMEM_BYTES);

    dim3 ggrid((N_NODES + 127) / 128, 2);
    const int attn_grid = (N_NODES + 7) / 8;

    prep_w<<<(WT_TOTAL + 255) / 256, 256>>>(W0, W1, W2, wbh, wbl);
    split_x<<<(N_NODES * 128 / 4 + 255) / 256, 256>>>(x, ah, al);

    gemm_mma<<<ggrid, 256, SMEM_BYTES>>>(ah, al, wbh, wbl, b0, hh, hl, 128, 0);
    attn_kernel<<<attn_grid, 256>>>(hh, hl, a2a, ah, al, nullptr);
    gemm_mma<<<ggrid, 256, SMEM_BYTES>>>(ah, al, wbh, wbl, b1, hh, hl, 256, 4 * WCH);
    attn_kernel<<<attn_grid, 256>>>(hh, hl, a2a, ah, al, nullptr);
    gemm_mma<<<ggrid, 256, SMEM_BYTES>>>(ah, al, wbh, wbl, b2, hh, hl, 256, 12 * WCH);
    attn_kernel<<<attn_grid, 256>>>(hh, hl, a2a, nullptr, nullptr, node_repr);

    readout_kernel<<<N_GRAPHS, 256>>>(node_repr, Wo1, bo1, Wo2, bo2, graph_repr, y);
}